// round 2
// baseline (speedup 1.0000x reference)
#include <cuda_runtime.h>
#include <cstdint>

// ============================================================
// MixedLinearV2: out[m, o] = sum_i x[m,i] * W[o,i] * M(band(o),band(i)) + b[o]*s(band(o))
//   x: [8192, 1024] f32, W: [6144, 1024] f32, out: [8192, 6144] f32
//   M == 0 for o >= 3072  ->  GEMM only over o in [0, 3072), zero-fill the rest.
// tcgen05 kind::tf32 SS GEMM, tile 128(M) x 256(N) x 32(K), double-buffered smem.
//
// The tcgen05 path is guarded to the arch-specific (sm_103a) device pass;
// the family-generic compute_103 PTX pass gets a SIMT fallback (never run).
// ============================================================

#if defined(__CUDA_ARCH_SPECIFIC__) || defined(__CUDA_ARCH_FAMILY_SPECIFIC__) || \
    defined(__CUDA_ARCH_FEAT_SM103_ALL) || defined(__CUDA_ARCH_FEAT_SM100_ALL)
#define USE_TCGEN05 1
#else
#define USE_TCGEN05 0
#endif

#define BM 128
#define BN 256
#define BK 32
#define NKIT 32          // 1024 / 32
#define THREADS 256

// smem layout (bytes). All MMA tiles 1024-aligned for SW128 descriptors.
#define SM_TMEM   0
#define SM_MBAR   16                  // two 8B mbarriers: +0, +8
#define SM_A0     1024                // 128 x 32 f32 = 16384
#define SM_A1     (1024 + 16384)      // 17408
#define SM_B0     (17408 + 16384)     // 33792, 256 x 32 f32 = 32768
#define SM_B1     (33792 + 32768)     // 66560
#define SM_TOTAL  (66560 + 32768)     // 99328

// idesc kind::tf32: dtype F32 (bits4-5 =1), atype TF32=2 (bits7-9), btype TF32=2 (bits10-12),
// N/8 at bits17-22, M/16 at bits24-28. K-major both.
static constexpr uint32_t IDESC_TF32 =
    (1u << 4) | (2u << 7) | (2u << 10) | ((BN / 8) << 17) | ((BM / 16) << 24);

// SW128 K-major descriptor base: layout=2, version=1, SBO=64 (1024B per 8-row group), LBO=1
static constexpr uint64_t DESC_BASE_SW128 =
    (uint64_t(2) << 61) | (uint64_t(1) << 46) | (uint64_t(64) << 32) | (uint64_t(1) << 16);
#define MK_DESC(addr) (DESC_BASE_SW128 | ((uint64_t)((addr) >> 4) & 0x3FFF))

// ---------------- PTX helpers (emitted only at guarded call sites) ----------------
static __device__ __forceinline__ uint32_t smem_u32(const void* p) {
    uint32_t a;
    asm("{ .reg .u64 t; cvta.to.shared.u64 t, %1; cvt.u32.u64 %0, t; }" : "=r"(a) : "l"(p));
    return a;
}
static __device__ __forceinline__ uint32_t elect_one() {
    uint32_t p;
    asm volatile("{ .reg .pred p; elect.sync _|p, 0xFFFFFFFF; selp.b32 %0, 1, 0, p; }" : "=r"(p));
    return p;
}
static __device__ __forceinline__ float cvt_tf32(float x) {
    uint32_t r;
    asm("cvt.rna.tf32.f32 %0, %1;" : "=r"(r) : "f"(x));
    return __uint_as_float(r);
}

#define MBARRIER_INIT(mbar, cnt) \
    asm volatile("mbarrier.init.shared.b64 [%0], %1;" :: "r"((uint32_t)(mbar)), "r"((uint32_t)(cnt)) : "memory")

#define MBARRIER_WAIT_PARITY(mbar_smem_addr, phase_parity) do { \
    uint32_t _mbar = (uint32_t)(mbar_smem_addr); \
    uint32_t _parity = (uint32_t)(phase_parity); \
    uint32_t _done; \
    asm volatile( \
        "{\n\t" \
        ".reg .pred p;\n\t" \
        "mbarrier.try_wait.parity.acquire.cta.shared::cta.b64 p, [%1], %2;\n\t" \
        "selp.b32 %0, 1, 0, p;\n\t" \
        "}" \
        : "=r"(_done) : "r"(_mbar), "r"(_parity) : "memory"); \
    if (!_done) { \
        asm volatile( \
            "{\n\t" \
            ".reg .pred P1;\n\t" \
            "WAIT_LOOP_%=:\n\t" \
            "mbarrier.try_wait.parity.acquire.cta.shared::cta.b64 P1, [%0], %1, 0x989680;\n\t" \
            "@P1 bra.uni WAIT_DONE_%=;\n\t" \
            "bra.uni WAIT_LOOP_%=;\n\t" \
            "WAIT_DONE_%=:\n\t" \
            "}" \
            :: "r"(_mbar), "r"(_parity) : "memory"); \
    } \
} while (0)

#define TCGEN05_ALLOC(smem_result_addr, nCols) \
    asm volatile("tcgen05.alloc.cta_group::1.sync.aligned.shared::cta.b32 [%0], %1;" \
        :: "r"((uint32_t)(smem_result_addr)), "r"((uint32_t)(nCols)) : "memory")
#define TCGEN05_DEALLOC(tmem_addr, nCols) \
    asm volatile("tcgen05.dealloc.cta_group::1.sync.aligned.b32 %0, %1;" \
        :: "r"(tmem_addr), "r"((uint32_t)(nCols)))
#define TCGEN05_RELINQUISH() \
    asm volatile("tcgen05.relinquish_alloc_permit.cta_group::1.sync.aligned;")
#define TCGEN05_COMMIT(mbar_smem_addr) \
    asm volatile("tcgen05.commit.cta_group::1.mbarrier::arrive::one.shared::cluster.b64 [%0];" \
        :: "r"((uint32_t)(mbar_smem_addr)) : "memory")
#define TCGEN05_WAIT_LD() \
    asm volatile("tcgen05.wait::ld.sync.aligned;" ::: "memory")
#define TCGEN05_FENCE_BEFORE() \
    asm volatile("tcgen05.fence::before_thread_sync;" ::: "memory")
#define TCGEN05_FENCE_AFTER() \
    asm volatile("tcgen05.fence::after_thread_sync;" ::: "memory")
#define FENCE_PROXY_ASYNC() \
    asm volatile("fence.proxy.async.shared::cta;" ::: "memory")

#define TCGEN05_LD_32X32B_X32(r, tmem_addr) \
    asm volatile( \
        "tcgen05.ld.sync.aligned.32x32b.x32.b32 " \
        "{%0, %1, %2, %3, %4, %5, %6, %7, " \
        " %8, %9, %10, %11, %12, %13, %14, %15, " \
        " %16, %17, %18, %19, %20, %21, %22, %23, " \
        " %24, %25, %26, %27, %28, %29, %30, %31}, [%32];" \
        : "=r"((r)[0]),  "=r"((r)[1]),  "=r"((r)[2]),  "=r"((r)[3]), \
          "=r"((r)[4]),  "=r"((r)[5]),  "=r"((r)[6]),  "=r"((r)[7]), \
          "=r"((r)[8]),  "=r"((r)[9]),  "=r"((r)[10]), "=r"((r)[11]), \
          "=r"((r)[12]), "=r"((r)[13]), "=r"((r)[14]), "=r"((r)[15]), \
          "=r"((r)[16]), "=r"((r)[17]), "=r"((r)[18]), "=r"((r)[19]), \
          "=r"((r)[20]), "=r"((r)[21]), "=r"((r)[22]), "=r"((r)[23]), \
          "=r"((r)[24]), "=r"((r)[25]), "=r"((r)[26]), "=r"((r)[27]), \
          "=r"((r)[28]), "=r"((r)[29]), "=r"((r)[30]), "=r"((r)[31]) \
        : "r"(tmem_addr))

static __device__ __forceinline__ void mma_tf32_cg1(
    uint32_t d_tmem, uint64_t a_desc, uint64_t b_desc, uint32_t idesc, uint32_t en) {
    asm volatile(
        "{\n\t"
        ".reg .pred p;\n\t"
        "setp.ne.u32 p, %4, 0;\n\t"
        "tcgen05.mma.cta_group::1.kind::tf32 [%0], %1, %2, %3, {%5, %5, %5, %5}, p;\n\t"
        "}"
        :: "r"(d_tmem), "l"(a_desc), "l"(b_desc), "r"(idesc), "r"(en), "r"(0u)
        : "memory");
}

// SW128 swizzle (Swizzle<3,4,3>): XOR bits[6:4] with bits[9:7]
static __device__ __forceinline__ uint32_t sw128(uint32_t off) {
    return off ^ ((off >> 3) & 0x70);
}

// ---------------- GEMM kernel ----------------
__global__ void __launch_bounds__(THREADS, 2)
gemm_tf32_kernel(const float* __restrict__ x, const float* __restrict__ wv,
                 const float* __restrict__ W, const float* __restrict__ bias,
                 float* __restrict__ out) {
    const int t   = threadIdx.x;
    const int n0  = blockIdx.x * BN;   // output col base (o), < 3072
    const int m0  = blockIdx.y * BM;   // output row base (b*1024+s)

    // ---- band scalars from weights (6 values, L2-cached broadcast) ----
    const float s45  = wv[4] + wv[5];
    const float s23  = wv[2] + wv[3] + s45;
    const float sall = wv[0] + wv[1] + s23;
    // N tile lies entirely in one o-band (boundaries 1536/2304 are multiples of 256)
    const int oband = (n0 >= 1536) + (n0 >= 2304);
    float mv0, mv1, mv2, bscale;
    if (oband == 0)      { mv0 = sall; mv1 = s23; mv2 = s45; bscale = sall; }
    else if (oband == 1) { mv0 = s23;  mv1 = s23; mv2 = s45; bscale = s23;  }
    else                 { mv0 = s45;  mv1 = s45; mv2 = s45; bscale = s45;  }

#if USE_TCGEN05
    extern __shared__ char smem[];
    const uint32_t sb = smem_u32(smem);
    const int wid = t >> 5;
    const int lid = t & 31;

    // ---- TMEM alloc + mbarrier init ----
    if (wid == 0) {
        if (elect_one()) {
            MBARRIER_INIT(sb + SM_MBAR + 0, 1);
            MBARRIER_INIT(sb + SM_MBAR + 8, 1);
        }
        TCGEN05_ALLOC(sb + SM_TMEM, 256);
    }
    __syncthreads();
    uint32_t tmem;
    asm volatile("ld.shared.b32 %0, [%1];" : "=r"(tmem) : "r"(sb + SM_TMEM));

    const uint32_t abuf[2] = { sb + SM_A0, sb + SM_A1 };
    const uint32_t bbuf[2] = { sb + SM_B0, sb + SM_B1 };

    const float* xbase = x + (size_t)m0 * 1024;
    const float* wbase = W + (size_t)n0 * 1024;

    // per-thread load/store tiling: A tile = 1024 float4 (4/thread), B tile = 2048 float4 (8/thread)
    auto load_regs = [&](int kc, float4* ar, float4* br) {
        const float* xa = xbase + kc * BK;
        const float* wa = wbase + kc * BK;
#pragma unroll
        for (int j = 0; j < 4; j++) {
            int idx = j * THREADS + t; int r = idx >> 3, q = idx & 7;
            ar[j] = *reinterpret_cast<const float4*>(xa + (size_t)r * 1024 + q * 4);
        }
#pragma unroll
        for (int j = 0; j < 8; j++) {
            int idx = j * THREADS + t; int r = idx >> 3, q = idx & 7;
            br[j] = *reinterpret_cast<const float4*>(wa + (size_t)r * 1024 + q * 4);
        }
    };
    auto sts_tile = [&](int s, const float4* ar, const float4* br, float m) {
        char* sm = smem;
        uint32_t aoff = abuf[s] - sb, boff = bbuf[s] - sb;
#pragma unroll
        for (int j = 0; j < 4; j++) {
            int idx = j * THREADS + t; int r = idx >> 3, q = idx & 7;
            float4 v = ar[j];
            v.x = cvt_tf32(v.x); v.y = cvt_tf32(v.y);
            v.z = cvt_tf32(v.z); v.w = cvt_tf32(v.w);
            *reinterpret_cast<float4*>(sm + aoff + sw128((uint32_t)(r * 128 + q * 16))) = v;
        }
#pragma unroll
        for (int j = 0; j < 8; j++) {
            int idx = j * THREADS + t; int r = idx >> 3, q = idx & 7;
            float4 v = br[j];
            v.x = cvt_tf32(v.x * m); v.y = cvt_tf32(v.y * m);
            v.z = cvt_tf32(v.z * m); v.w = cvt_tf32(v.w * m);
            *reinterpret_cast<float4*>(sm + boff + sw128((uint32_t)(r * 128 + q * 16))) = v;
        }
    };
    auto mval = [&](int kc) -> float {
        return (kc < 16) ? mv0 : (kc < 24 ? mv1 : mv2);
    };

    // ---- prologue: tile 0 -> buf 0 ----
    {
        float4 ar[4], br[8];
        load_regs(0, ar, br);
        sts_tile(0, ar, br, mval(0));
        FENCE_PROXY_ASYNC();
    }
    __syncthreads();

    int ph[2] = {0, 0};
#pragma unroll 1
    for (int it = 0; it < NKIT; ++it) {
        const int cur = it & 1, nxt = cur ^ 1;
        const bool more = (it + 1 < NKIT);
        float4 ar[4], br[8];
        if (more) load_regs(it + 1, ar, br);

        if (wid == 0 && elect_one()) {
            const uint64_t ad = MK_DESC(abuf[cur]);
            const uint64_t bd = MK_DESC(bbuf[cur]);
#pragma unroll
            for (int ks = 0; ks < 4; ++ks)  // 4 x K=8 tf32 steps = BK 32
                mma_tf32_cg1(tmem, ad + ks * 2, bd + ks * 2, IDESC_TF32,
                             (uint32_t)(it > 0 || ks > 0));
            TCGEN05_COMMIT(sb + SM_MBAR + cur * 8);
        }

        if (more) {
            if (it >= 1) {  // wait MMA(it-1) done before overwriting buf[nxt]
                MBARRIER_WAIT_PARITY(sb + SM_MBAR + nxt * 8, ph[nxt]);
                ph[nxt] ^= 1;
            }
            sts_tile(nxt, ar, br, mval(it + 1));
            FENCE_PROXY_ASYNC();
        }
        __syncthreads();
    }

    // last commit was on mbar[(NKIT-1)&1] == mbar[1]
    MBARRIER_WAIT_PARITY(sb + SM_MBAR + 8, ph[1]);
    TCGEN05_FENCE_AFTER();

    // ---- epilogue: 8 warps, wg0 -> cols [0,128), wg1 -> cols [128,256) ----
    const int wg  = wid >> 2;
    const int row = (wid & 3) * 32 + lid;          // tile M row (TMEM lane)
    float* orow = out + (size_t)(m0 + row) * 6144 + n0;
#pragma unroll
    for (int r4 = 0; r4 < 4; ++r4) {
        const int cb = wg * 128 + r4 * 32;
        uint32_t dr[32];
        TCGEN05_LD_32X32B_X32(dr, tmem + cb);
        TCGEN05_WAIT_LD();
#pragma unroll
        for (int c = 0; c < 32; c += 4) {
            const int col = n0 + cb + c;
            float4 v;
            v.x = __uint_as_float(dr[c + 0]) + bias[col + 0] * bscale;
            v.y = __uint_as_float(dr[c + 1]) + bias[col + 1] * bscale;
            v.z = __uint_as_float(dr[c + 2]) + bias[col + 2] * bscale;
            v.w = __uint_as_float(dr[c + 3]) + bias[col + 3] * bscale;
            *reinterpret_cast<float4*>(orow + cb + c) = v;
        }
    }
    TCGEN05_FENCE_BEFORE();
    __syncthreads();
    if (wid == 0) {
        TCGEN05_RELINQUISH();
        TCGEN05_DEALLOC(tmem, 256);
    }
#else
    // ---- SIMT fallback for the family-generic PTX pass (never run on GB300;
    //      the driver loads the sm_103a cubin). Correct but slow. ----
    for (int e = t; e < BM * BN; e += THREADS) {
        const int r = e / BN, c = e % BN;
        const float* xr = x + (size_t)(m0 + r) * 1024;
        const float* wr = W + (size_t)(n0 + c) * 1024;
        float acc = 0.f;
        for (int k = 0; k < 1024; ++k) {
            const float m = (k < 512) ? mv0 : (k < 768 ? mv1 : mv2);
            acc += xr[k] * wr[k] * m;
        }
        out[(size_t)(m0 + r) * 6144 + n0 + c] = acc + bias[n0 + c] * bscale;
    }
#endif
}

// ---------------- zero-fill for o in [3072, 6144) ----------------
__global__ void fill_tail_kernel(float* __restrict__ out) {
    const size_t total = (size_t)8192 * 768;  // float4 count
    size_t idx = (size_t)blockIdx.x * blockDim.x + threadIdx.x;
    if (idx >= total) return;
    const size_t r = idx / 768, q = idx % 768;
    *reinterpret_cast<float4*>(out + r * 6144 + 3072 + q * 4) =
        make_float4(0.f, 0.f, 0.f, 0.f);
}

// ---------------- launcher ----------------
extern "C" void kernel_launch(void* const* d_in, const int* in_sizes, int n_in,
                              void* d_out, int out_size) {
    const float *x = nullptr, *wv = nullptr, *W = nullptr, *b = nullptr;
    for (int i = 0; i < n_in; ++i) {
        switch (in_sizes[i]) {
            case 8388608: x  = (const float*)d_in[i]; break;  // 8*1024*1024
            case 6:       wv = (const float*)d_in[i]; break;
            case 6291456: W  = (const float*)d_in[i]; break;  // 6144*1024
            case 6144:    b  = (const float*)d_in[i]; break;
        }
    }
    if (!x)  x  = (const float*)d_in[0];
    if (!wv) wv = (const float*)d_in[1];
    if (!W)  W  = (const float*)d_in[2];
    if (!b)  b  = (const float*)d_in[3];
    float* out = (float*)d_out;

    cudaFuncSetAttribute(gemm_tf32_kernel,
                         cudaFuncAttributeMaxDynamicSharedMemorySize, SM_TOTAL);

    // zero the dead half of the output: cols [3072, 6144)
    fill_tail_kernel<<<(8192 * 768 + 255) / 256, 256>>>(out);

    // GEMM over cols [0, 3072): grid 12 x 64 = 768 CTAs
    gemm_tf32_kernel<<<dim3(3072 / BN, 8192 / BM), THREADS, SM_TOTAL>>>(x, wv, W, b, out);
}

// round 3
// speedup vs baseline: 1.7634x; 1.7634x over previous
#include <cuda_runtime.h>
#include <cstdint>

// ============================================================
// MixedLinearV2 = GEMM out[8192,6144] = x[8192,1024] @ (W*M)^T + b*rowmask
//   M == 0 for o >= 3072 -> GEMM over o in [0,3072) only, zero-fill rest.
// R3: prepass folds mask+tf32-rounding into scratch (g_xr, g_wr), then a
// pure 4-stage cp.async-pipelined tcgen05 tf32 GEMM (no syncthreads in loop).
// ============================================================

#if defined(__CUDA_ARCH_SPECIFIC__) || defined(__CUDA_ARCH_FAMILY_SPECIFIC__) || \
    defined(__CUDA_ARCH_FEAT_SM103_ALL) || defined(__CUDA_ARCH_FEAT_SM100_ALL)
#define USE_TCGEN05 1
#else
#define USE_TCGEN05 0
#endif

#define BM 128
#define BN 256
#define BK 32
#define NKIT 32           // 1024 / 32
#define STAGES 4
#define THREADS 256
#define NPROD 224         // warps 1..7 produce

// ---- scratch (static device globals: allowed, no allocation) ----
__device__ float g_xr[8192 * 1024];   // 32 MB, tf32-rounded x
__device__ float g_wr[3072 * 1024];   // 12 MB, tf32-rounded W * mask

// ---- smem layout (bytes); tiles 1024-aligned for SW128 descriptors ----
#define SM_TMEM    0
#define SM_FULL(s) (16 + (s) * 8)
#define SM_EMPTY(s)(48 + (s) * 8)
#define SM_FINAL   80
#define SM_A(s)    (1024 + (s) * 16384)          // 128x32 f32 = 16 KB
#define SM_B(s)    (66560 + (s) * 32768)         // 256x32 f32 = 32 KB
#define SM_TOTAL   197632                        // 1 KB hdr + 64 KB A + 128 KB B

// idesc kind::tf32: dtype F32(bit4), atype TF32=2(7-9), btype TF32=2(10-12),
// N/8 @17, M/16 @24. K-major both.
static constexpr uint32_t IDESC_TF32 =
    (1u << 4) | (2u << 7) | (2u << 10) | ((BN / 8) << 17) | ((BM / 16) << 24);

// SW128 K-major: layout=2, version=1, SBO=64, LBO=1
static constexpr uint64_t DESC_BASE_SW128 =
    (uint64_t(2) << 61) | (uint64_t(1) << 46) | (uint64_t(64) << 32) | (uint64_t(1) << 16);
#define MK_DESC(addr) (DESC_BASE_SW128 | ((uint64_t)((addr) >> 4) & 0x3FFF))

// ---------------- PTX helpers ----------------
static __device__ __forceinline__ uint32_t smem_u32(const void* p) {
    uint32_t a;
    asm("{ .reg .u64 t; cvta.to.shared.u64 t, %1; cvt.u32.u64 %0, t; }" : "=r"(a) : "l"(p));
    return a;
}
static __device__ __forceinline__ uint32_t elect_one() {
    uint32_t p;
    asm volatile("{ .reg .pred p; elect.sync _|p, 0xFFFFFFFF; selp.b32 %0, 1, 0, p; }" : "=r"(p));
    return p;
}
static __device__ __forceinline__ float cvt_tf32(float x) {
    uint32_t r;
    asm("cvt.rna.tf32.f32 %0, %1;" : "=r"(r) : "f"(x));
    return __uint_as_float(r);
}

#define MBARRIER_INIT(mbar, cnt) \
    asm volatile("mbarrier.init.shared.b64 [%0], %1;" :: "r"((uint32_t)(mbar)), "r"((uint32_t)(cnt)) : "memory")

#define MBARRIER_WAIT_PARITY(mbar_smem_addr, phase_parity) do { \
    uint32_t _mbar = (uint32_t)(mbar_smem_addr); \
    uint32_t _parity = (uint32_t)(phase_parity); \
    uint32_t _done; \
    asm volatile( \
        "{\n\t" \
        ".reg .pred p;\n\t" \
        "mbarrier.try_wait.parity.acquire.cta.shared::cta.b64 p, [%1], %2;\n\t" \
        "selp.b32 %0, 1, 0, p;\n\t" \
        "}" \
        : "=r"(_done) : "r"(_mbar), "r"(_parity) : "memory"); \
    if (!_done) { \
        asm volatile( \
            "{\n\t" \
            ".reg .pred P1;\n\t" \
            "WAIT_LOOP_%=:\n\t" \
            "mbarrier.try_wait.parity.acquire.cta.shared::cta.b64 P1, [%0], %1, 0x989680;\n\t" \
            "@P1 bra.uni WAIT_DONE_%=;\n\t" \
            "bra.uni WAIT_LOOP_%=;\n\t" \
            "WAIT_DONE_%=:\n\t" \
            "}" \
            :: "r"(_mbar), "r"(_parity) : "memory"); \
    } \
} while (0)

#define CP_ASYNC_CG(dst, src) \
    asm volatile("cp.async.cg.shared.global [%0], [%1], 16;" :: "r"((uint32_t)(dst)), "l"(src) : "memory")
#define CP_ASYNC_ARRIVE(mbar) \
    asm volatile("cp.async.mbarrier.arrive.noinc.shared::cta.b64 [%0];" :: "r"((uint32_t)(mbar)) : "memory")

#define TCGEN05_ALLOC(smem_result_addr, nCols) \
    asm volatile("tcgen05.alloc.cta_group::1.sync.aligned.shared::cta.b32 [%0], %1;" \
        :: "r"((uint32_t)(smem_result_addr)), "r"((uint32_t)(nCols)) : "memory")
#define TCGEN05_DEALLOC(tmem_addr, nCols) \
    asm volatile("tcgen05.dealloc.cta_group::1.sync.aligned.b32 %0, %1;" \
        :: "r"(tmem_addr), "r"((uint32_t)(nCols)))
#define TCGEN05_RELINQUISH() \
    asm volatile("tcgen05.relinquish_alloc_permit.cta_group::1.sync.aligned;")
#define TCGEN05_COMMIT(mbar_smem_addr) \
    asm volatile("tcgen05.commit.cta_group::1.mbarrier::arrive::one.shared::cluster.b64 [%0];" \
        :: "r"((uint32_t)(mbar_smem_addr)) : "memory")
#define TCGEN05_WAIT_LD() \
    asm volatile("tcgen05.wait::ld.sync.aligned;" ::: "memory")
#define TCGEN05_FENCE_BEFORE() \
    asm volatile("tcgen05.fence::before_thread_sync;" ::: "memory")
#define TCGEN05_FENCE_AFTER() \
    asm volatile("tcgen05.fence::after_thread_sync;" ::: "memory")
#define FENCE_PROXY_ASYNC() \
    asm volatile("fence.proxy.async.shared::cta;" ::: "memory")

#define TCGEN05_LD_32X32B_X32(r, tmem_addr) \
    asm volatile( \
        "tcgen05.ld.sync.aligned.32x32b.x32.b32 " \
        "{%0, %1, %2, %3, %4, %5, %6, %7, " \
        " %8, %9, %10, %11, %12, %13, %14, %15, " \
        " %16, %17, %18, %19, %20, %21, %22, %23, " \
        " %24, %25, %26, %27, %28, %29, %30, %31}, [%32];" \
        : "=r"((r)[0]),  "=r"((r)[1]),  "=r"((r)[2]),  "=r"((r)[3]), \
          "=r"((r)[4]),  "=r"((r)[5]),  "=r"((r)[6]),  "=r"((r)[7]), \
          "=r"((r)[8]),  "=r"((r)[9]),  "=r"((r)[10]), "=r"((r)[11]), \
          "=r"((r)[12]), "=r"((r)[13]), "=r"((r)[14]), "=r"((r)[15]), \
          "=r"((r)[16]), "=r"((r)[17]), "=r"((r)[18]), "=r"((r)[19]), \
          "=r"((r)[20]), "=r"((r)[21]), "=r"((r)[22]), "=r"((r)[23]), \
          "=r"((r)[24]), "=r"((r)[25]), "=r"((r)[26]), "=r"((r)[27]), \
          "=r"((r)[28]), "=r"((r)[29]), "=r"((r)[30]), "=r"((r)[31]) \
        : "r"(tmem_addr))

static __device__ __forceinline__ void mma_tf32_cg1(
    uint32_t d_tmem, uint64_t a_desc, uint64_t b_desc, uint32_t idesc, uint32_t en) {
    asm volatile(
        "{\n\t"
        ".reg .pred p;\n\t"
        "setp.ne.u32 p, %4, 0;\n\t"
        "tcgen05.mma.cta_group::1.kind::tf32 [%0], %1, %2, %3, {%5, %5, %5, %5}, p;\n\t"
        "}"
        :: "r"(d_tmem), "l"(a_desc), "l"(b_desc), "r"(idesc), "r"(en), "r"(0u)
        : "memory");
}

static __device__ __forceinline__ uint32_t sw128(uint32_t off) {
    return off ^ ((off >> 3) & 0x70);
}

// ---------------- prepass: round x -> g_xr ----------------
__global__ void prep_x_kernel(const float* __restrict__ x) {
    const size_t i = ((size_t)blockIdx.x * blockDim.x + threadIdx.x) * 4;
    float4 v = *reinterpret_cast<const float4*>(x + i);
    v.x = cvt_tf32(v.x); v.y = cvt_tf32(v.y); v.z = cvt_tf32(v.z); v.w = cvt_tf32(v.w);
    *reinterpret_cast<float4*>(g_xr + i) = v;
}

// ---------------- prepass: fold mask into W, round -> g_wr ----------------
__global__ void prep_w_kernel(const float* __restrict__ W, const float* __restrict__ wv) {
    const float s45  = wv[4] + wv[5];
    const float s23  = wv[2] + wv[3] + s45;
    const float sall = wv[0] + wv[1] + s23;
    const size_t i = ((size_t)blockIdx.x * blockDim.x + threadIdx.x) * 4;  // < 3072*1024
    const int o = (int)(i >> 10);
    const int k = (int)(i & 1023);
    const int ob = (o >= 1536) + (o >= 2304);
    float m;
    if (k >= 768)       m = s45;
    else if (k >= 512)  m = (ob == 0) ? s23 : (ob == 1 ? s23 : s45);
    else                m = (ob == 0) ? sall : (ob == 1 ? s23 : s45);
    float4 v = *reinterpret_cast<const float4*>(W + i);
    v.x = cvt_tf32(v.x * m); v.y = cvt_tf32(v.y * m);
    v.z = cvt_tf32(v.z * m); v.w = cvt_tf32(v.w * m);
    *reinterpret_cast<float4*>(g_wr + i) = v;
}

// ---------------- GEMM kernel ----------------
__global__ void __launch_bounds__(THREADS, 1)
gemm_tf32_kernel(const float* __restrict__ x, const float* __restrict__ wv,
                 const float* __restrict__ W, const float* __restrict__ bias,
                 float* __restrict__ out) {
    const int t  = threadIdx.x;
    const int n0 = blockIdx.x * BN;
    const int m0 = blockIdx.y * BM;

    const float s45  = wv[4] + wv[5];
    const float s23  = wv[2] + wv[3] + s45;
    const float sall = wv[0] + wv[1] + s23;
    const int oband = (n0 >= 1536) + (n0 >= 2304);
    const float bscale = (oband == 0) ? sall : (oband == 1 ? s23 : s45);

#if USE_TCGEN05
    extern __shared__ char smem[];
    const uint32_t sb = smem_u32(smem);
    const int wid = t >> 5;
    const int lid = t & 31;

    if (wid == 0) {
        if (elect_one()) {
#pragma unroll
            for (int s = 0; s < STAGES; ++s) {
                MBARRIER_INIT(sb + SM_FULL(s), NPROD);
                MBARRIER_INIT(sb + SM_EMPTY(s), 1);
            }
            MBARRIER_INIT(sb + SM_FINAL, 1);
        }
        TCGEN05_ALLOC(sb + SM_TMEM, 256);
    }
    __syncthreads();
    uint32_t tmem;
    asm volatile("ld.shared.b32 %0, [%1];" : "=r"(tmem) : "r"(sb + SM_TMEM));

    if (wid == 0) {
        // ---- MMA issuer (one elected lane) ----
        if (elect_one()) {
            int fph[STAGES] = {0, 0, 0, 0};
#pragma unroll 1
            for (int it = 0; it < NKIT; ++it) {
                const int s = it & (STAGES - 1);
                MBARRIER_WAIT_PARITY(sb + SM_FULL(s), fph[s]);
                fph[s] ^= 1;
                FENCE_PROXY_ASYNC();
                const uint64_t ad = MK_DESC(sb + SM_A(s));
                const uint64_t bd = MK_DESC(sb + SM_B(s));
#pragma unroll
                for (int ks = 0; ks < 4; ++ks)
                    mma_tf32_cg1(tmem, ad + ks * 2, bd + ks * 2, IDESC_TF32,
                                 (uint32_t)(it > 0 || ks > 0));
                TCGEN05_COMMIT(sb + SM_EMPTY(s));
            }
            TCGEN05_COMMIT(sb + SM_FINAL);
        }
    } else {
        // ---- producers: warps 1..7, cp.async pipeline ----
        const int p = t - 32;  // 0..223
        int eph[STAGES] = {0, 0, 0, 0};
        const float* abase = g_xr + (size_t)m0 * 1024;
        const float* bbase = g_wr + (size_t)n0 * 1024;
#pragma unroll 1
        for (int nt = 0; nt < NKIT; ++nt) {
            const int s = nt & (STAGES - 1);
            if (nt >= STAGES) {
                MBARRIER_WAIT_PARITY(sb + SM_EMPTY(s), eph[s]);
                eph[s] ^= 1;
            }
            const float* ak = abase + nt * BK;
            const float* bk = bbase + nt * BK;
            const uint32_t sa = sb + SM_A(s);
            const uint32_t sbb = sb + SM_B(s);
#pragma unroll
            for (int j = 0; j < 14; ++j) {
                const int i = p + j * NPROD;
                if (i >= 3072) break;
                if (i < 1024) {
                    const int r = i >> 3, q = i & 7;
                    CP_ASYNC_CG(sa + sw128((uint32_t)(r * 128 + q * 16)),
                                ak + (size_t)r * 1024 + q * 4);
                } else {
                    const int i2 = i - 1024;
                    const int r = i2 >> 3, q = i2 & 7;
                    CP_ASYNC_CG(sbb + sw128((uint32_t)(r * 128 + q * 16)),
                                bk + (size_t)r * 1024 + q * 4);
                }
            }
            CP_ASYNC_ARRIVE(sb + SM_FULL(s));
        }
    }

    // ---- all threads: wait for all MMAs, then epilogue ----
    MBARRIER_WAIT_PARITY(sb + SM_FINAL, 0);
    TCGEN05_FENCE_AFTER();

    const int wg  = wid >> 2;
    const int row = (wid & 3) * 32 + lid;
    float* orow = out + (size_t)(m0 + row) * 6144 + n0;
#pragma unroll
    for (int r4 = 0; r4 < 4; ++r4) {
        const int cb = wg * 128 + r4 * 32;
        uint32_t dr[32];
        TCGEN05_LD_32X32B_X32(dr, tmem + cb);
        TCGEN05_WAIT_LD();
#pragma unroll
        for (int c = 0; c < 32; c += 4) {
            const int col = n0 + cb + c;
            float4 v;
            v.x = __uint_as_float(dr[c + 0]) + bias[col + 0] * bscale;
            v.y = __uint_as_float(dr[c + 1]) + bias[col + 1] * bscale;
            v.z = __uint_as_float(dr[c + 2]) + bias[col + 2] * bscale;
            v.w = __uint_as_float(dr[c + 3]) + bias[col + 3] * bscale;
            *reinterpret_cast<float4*>(orow + cb + c) = v;
        }
    }
    TCGEN05_FENCE_BEFORE();
    __syncthreads();
    if (wid == 0) {
        TCGEN05_RELINQUISH();
        TCGEN05_DEALLOC(tmem, 256);
    }
#else
    // SIMT fallback for the family-generic PTX pass (never executed on GB300).
    float mv0, mv1, mv2;
    if (oband == 0)      { mv0 = sall; mv1 = s23; mv2 = s45; }
    else if (oband == 1) { mv0 = s23;  mv1 = s23; mv2 = s45; }
    else                 { mv0 = s45;  mv1 = s45; mv2 = s45; }
    for (int e = t; e < BM * BN; e += THREADS) {
        const int r = e / BN, c = e % BN;
        const float* xr = x + (size_t)(m0 + r) * 1024;
        const float* wr = W + (size_t)(n0 + c) * 1024;
        float acc = 0.f;
        for (int k = 0; k < 1024; ++k) {
            const float m = (k < 512) ? mv0 : (k < 768 ? mv1 : mv2);
            acc += xr[k] * wr[k] * m;
        }
        out[(size_t)(m0 + r) * 6144 + n0 + c] = acc + bias[n0 + c] * bscale;
    }
#endif
}

// ---------------- zero-fill for o in [3072, 6144) ----------------
__global__ void fill_tail_kernel(float* __restrict__ out) {
    const size_t total = (size_t)8192 * 768;  // float4 count
    size_t idx = (size_t)blockIdx.x * blockDim.x + threadIdx.x;
    if (idx >= total) return;
    const size_t r = idx / 768, q = idx % 768;
    *reinterpret_cast<float4*>(out + r * 6144 + 3072 + q * 4) =
        make_float4(0.f, 0.f, 0.f, 0.f);
}

// ---------------- launcher ----------------
extern "C" void kernel_launch(void* const* d_in, const int* in_sizes, int n_in,
                              void* d_out, int out_size) {
    const float *x = nullptr, *wv = nullptr, *W = nullptr, *b = nullptr;
    for (int i = 0; i < n_in; ++i) {
        switch (in_sizes[i]) {
            case 8388608: x  = (const float*)d_in[i]; break;
            case 6:       wv = (const float*)d_in[i]; break;
            case 6291456: W  = (const float*)d_in[i]; break;
            case 6144:    b  = (const float*)d_in[i]; break;
        }
    }
    if (!x)  x  = (const float*)d_in[0];
    if (!wv) wv = (const float*)d_in[1];
    if (!W)  W  = (const float*)d_in[2];
    if (!b)  b  = (const float*)d_in[3];
    float* out = (float*)d_out;

    cudaFuncSetAttribute(gemm_tf32_kernel,
                         cudaFuncAttributeMaxDynamicSharedMemorySize, SM_TOTAL);

    // prepass: tf32-round x; fold mask into W and round
    prep_x_kernel<<<8192, 256>>>(x);                       // 8192*1024 / (256*4)
    prep_w_kernel<<<3072, 256>>>(W, wv);                   // 3072*1024 / (256*4)
    // zero the dead half of the output: cols [3072, 6144)
    fill_tail_kernel<<<(8192 * 768 + 255) / 256, 256>>>(out);
    // GEMM over cols [0, 3072)
    gemm_tf32_kernel<<<dim3(3072 / BN, 8192 / BM), THREADS, SM_TOTAL>>>(x, wv, W, b, out);
}